// round 17
// baseline (speedup 1.0000x reference)
#include <cuda_runtime.h>
#include <cuda_bf16.h>
#include <math.h>
#include <stdint.h>

// ---------------- shapes ----------------
#define B_    8
#define L_    1024
#define F_    1024
#define H_    256
#define NH_   8
#define LBL_  4766
#define ROWS_ (B_*L_)      // 8192
#define OH_   (NH_*H_)     // 2048

// ---------------- scratch ----------------
__device__ float g_x2[ROWS_*H_];
__device__ float g_att[B_*NH_*L_];
__device__ float g_part[B_*16*NH_*H_];
__device__ float g_h[B_*OH_];
__device__ float g_h1[B_*OH_];
__device__ __align__(16) float g_p[LBL_*B_];   // pT[j][8]
__device__ float g_op1[16*8*OH_];
__device__ float g_op2[16*8*LBL_];
__device__ __align__(16) unsigned short g_Ahi[ROWS_*F_];
__device__ __align__(16) unsigned short g_Alo[ROWS_*F_];
__device__ __align__(16) unsigned short g_A2hi[ROWS_*H_];
__device__ __align__(16) unsigned short g_A2lo[ROWS_*H_];
__device__ __align__(16) unsigned short g_Whi[H_*F_];
__device__ __align__(16) unsigned short g_Wlo[H_*F_];
__device__ __align__(16) unsigned short g_W2hi[H_*H_];
__device__ __align__(16) unsigned short g_W2lo[H_*H_];

// ---------------- helpers ----------------
__device__ __forceinline__ float leaky(float v) { return v >= 0.f ? v : 0.01f * v; }
__device__ __forceinline__ unsigned short f2bf(float f) {
    return __bfloat16_as_ushort(__float2bfloat16_rn(f));
}
__device__ __forceinline__ float bf2f(unsigned short u) {
    return __bfloat162float(__ushort_as_bfloat16(u));
}
__device__ __forceinline__ uint32_t smem_u32(const void* p) {
    uint32_t a;
    asm("{ .reg .u64 t; cvta.to.shared.u64 t, %1; cvt.u32.u64 %0, t; }" : "=r"(a) : "l"(p));
    return a;
}
__device__ __forceinline__ void cp16(uint32_t dst, const void* src) {
    asm volatile("cp.async.cg.shared.global [%0], [%1], 16;" :: "r"(dst), "l"(src));
}
#define CP_COMMIT() asm volatile("cp.async.commit_group;" ::: "memory")
#define CP_WAIT(n)  asm volatile("cp.async.wait_group %0;" :: "n"(n) : "memory")

__device__ __forceinline__ void mma_bf16(float* d, const uint32_t* a, const uint32_t* b) {
    asm volatile(
        "mma.sync.aligned.m16n8k16.row.col.f32.bf16.bf16.f32 "
        "{%0,%1,%2,%3}, {%4,%5,%6,%7}, {%8,%9}, {%0,%1,%2,%3};"
        : "+f"(d[0]), "+f"(d[1]), "+f"(d[2]), "+f"(d[3])
        : "r"(a[0]), "r"(a[1]), "r"(a[2]), "r"(a[3]), "r"(b[0]), "r"(b[1]));
}

__device__ __forceinline__ void pack8(const float* v, uint4& hi, uint4& lo) {
    unsigned short h[8], l[8];
    #pragma unroll
    for (int q = 0; q < 8; q++) {
        h[q] = f2bf(v[q]);
        l[q] = f2bf(v[q] - bf2f(h[q]));
    }
    hi.x = h[0] | (h[1] << 16); hi.y = h[2] | (h[3] << 16);
    hi.z = h[4] | (h[5] << 16); hi.w = h[6] | (h[7] << 16);
    lo.x = l[0] | (l[1] << 16); lo.y = l[2] | (l[3] << 16);
    lo.z = l[4] | (l[5] << 16); lo.w = l[6] | (l[7] << 16);
}

// ---------------- convA 1024: 2 rows/block, 8 elems/thread ----------------
__global__ __launch_bounds__(256) void convA1024(const float* __restrict__ in,
                                                 unsigned short* __restrict__ hi,
                                                 unsigned short* __restrict__ lo,
                                                 const float* __restrict__ g,
                                                 const float* __restrict__ b) {
    __shared__ float ws[2][8];
    int t = threadIdx.x;
    int half = t >> 7, tt = t & 127;
    int wir = (tt >> 5), lane = t & 31;
    size_t row = (size_t)blockIdx.x * 2 + half;
    const float4* rp = (const float4*)(in + row * 1024);
    float4 v0 = rp[tt * 2], v1 = rp[tt * 2 + 1];
    float sum = v0.x+v0.y+v0.z+v0.w + v1.x+v1.y+v1.z+v1.w;
    float sq  = v0.x*v0.x+v0.y*v0.y+v0.z*v0.z+v0.w*v0.w
              + v1.x*v1.x+v1.y*v1.y+v1.z*v1.z+v1.w*v1.w;
    #pragma unroll
    for (int o = 16; o > 0; o >>= 1) {
        sum += __shfl_xor_sync(0xffffffffu, sum, o);
        sq  += __shfl_xor_sync(0xffffffffu, sq,  o);
    }
    if (lane == 0) { ws[half][wir] = sum; ws[half][4 + wir] = sq; }
    __syncthreads();
    float s4 = ws[half][0] + ws[half][1] + ws[half][2] + ws[half][3];
    float q4 = ws[half][4] + ws[half][5] + ws[half][6] + ws[half][7];
    float m   = s4 * (1.f/1024.f);
    float inv = rsqrtf(q4 * (1.f/1024.f) - m * m + 1e-6f);
    int c0 = tt * 8;
    float4 g0 = *(const float4*)(g + c0), g1 = *(const float4*)(g + c0 + 4);
    float4 b0 = *(const float4*)(b + c0), b1 = *(const float4*)(b + c0 + 4);
    float v[8];
    v[0]=(v0.x-m)*inv*g0.x+b0.x; v[1]=(v0.y-m)*inv*g0.y+b0.y;
    v[2]=(v0.z-m)*inv*g0.z+b0.z; v[3]=(v0.w-m)*inv*g0.w+b0.w;
    v[4]=(v1.x-m)*inv*g1.x+b1.x; v[5]=(v1.y-m)*inv*g1.y+b1.y;
    v[6]=(v1.z-m)*inv*g1.z+b1.z; v[7]=(v1.w-m)*inv*g1.w+b1.w;
    uint4 ph, pl;
    pack8(v, ph, pl);
    ((uint4*)(hi + row * 1024))[tt] = ph;
    ((uint4*)(lo + row * 1024))[tt] = pl;
}

// ---------------- convW both: transpose to [n][k] bf16 hi/lo ------------------
// z=0: w_in [1024,256]; z=1: w_h [256,256]
__global__ __launch_bounds__(256) void convWB(const float* __restrict__ w1g,
                                              unsigned short* __restrict__ w1hi,
                                              unsigned short* __restrict__ w1lo,
                                              const float* __restrict__ w2g,
                                              unsigned short* __restrict__ w2hi,
                                              unsigned short* __restrict__ w2lo) {
    __shared__ float s[32][33];
    int z = blockIdx.z;
    int K = z ? 256 : 1024;
    const float* w = z ? w2g : w1g;
    unsigned short* whi = z ? w2hi : w1hi;
    unsigned short* wlo = z ? w2lo : w1lo;
    int t = threadIdx.x;
    int n0 = blockIdx.x * 32, k0 = blockIdx.y * 32;
    if (k0 >= K) return;
    const int N = 256;
    #pragma unroll
    for (int i = 0; i < 4; i++) {
        int idx = i * 256 + t;
        int kr = idx >> 5, nc = idx & 31;
        s[kr][nc] = w[(size_t)(k0 + kr) * N + n0 + nc];
    }
    __syncthreads();
    #pragma unroll
    for (int i = 0; i < 4; i++) {
        int idx = i * 256 + t;
        int nr = idx >> 5, kc = idx & 31;
        float v = s[kc][nr];
        unsigned short h = f2bf(v);
        size_t o = (size_t)(n0 + nr) * K + k0 + kc;
        whi[o] = h;
        wlo[o] = f2bf(v - bf2f(h));
    }
}

// ============ HMMA bf16 wide GEMM: 128x256 tile, fused LN epilogue ============
// EPI 0: out = bf16 hi/lo planes of LN(leaky(A@W^T+bias))  (feeds next GEMM)
// EPI 1: out = fp32 LN(leaky(A@W^T+bias)) to xout
#define PITCH 72
#define APL (128*PITCH)          // A plane elems
#define BPL (256*PITCH)          // B plane elems
#define WBUFE (2*APL + 2*BPL)    // elems per buffer = 55296
#define WGS (2*WBUFE*2)          // bytes = 221184

template<int EPI>
__global__ __launch_bounds__(512) void gemm_wide(const unsigned short* __restrict__ Ahi,
                                                 const unsigned short* __restrict__ Alo,
                                                 const unsigned short* __restrict__ Bhi,
                                                 const unsigned short* __restrict__ Blo,
                                                 const float* __restrict__ bias,
                                                 const float* __restrict__ lg,
                                                 const float* __restrict__ lb,
                                                 unsigned short* __restrict__ Ohi,
                                                 unsigned short* __restrict__ Olo,
                                                 float* __restrict__ xout,
                                                 int K) {
    extern __shared__ unsigned short sm[];
    uint32_t sbase = smem_u32(sm);

    int t = threadIdx.x, wid = t >> 5, lane = t & 31;
    int wm = wid >> 3, wn = wid & 7;            // 2 x 8 warp grid, 64x32 tiles
    int bm = blockIdx.x * 128;
    int fr = lane >> 2, fc = lane & 3;

    // loaders
    int arow = t >> 2, aq = (t & 3) * 16;       // A: 128 rows, 16 k per quarter
    int brow = t >> 1, bh = (t & 1) * 32;       // B: 256 rows, 32 k per half
    const unsigned short* pAhi = Ahi + (size_t)(bm + arow) * K + aq;
    const unsigned short* pAlo = Alo + (size_t)(bm + arow) * K + aq;
    const unsigned short* pBhi = Bhi + (size_t)brow * K + bh;
    const unsigned short* pBlo = Blo + (size_t)brow * K + bh;
    uint32_t dAhi = sbase + 2u * (uint32_t)(arow * PITCH + aq);
    uint32_t dBhi = sbase + 2u * (uint32_t)(2 * APL + brow * PITCH + bh);

    auto load_chunk = [&](int c, int buf) {
        uint32_t db = 2u * (uint32_t)(buf * WBUFE);
        int ko = c * 64;
        cp16(dAhi + db,                 pAhi + ko);
        cp16(dAhi + db + 16,            pAhi + ko + 8);
        cp16(dAhi + db + 2*APL,         pAlo + ko);
        cp16(dAhi + db + 2*APL + 16,    pAlo + ko + 8);
        #pragma unroll
        for (int j = 0; j < 4; j++) {
            cp16(dBhi + db + j * 16,           pBhi + ko + j * 8);
            cp16(dBhi + db + 2*BPL + j * 16,   pBlo + ko + j * 8);
        }
    };

    float acc[4][4][4] = {};

    int NC = K / 64;
    load_chunk(0, 0);
    CP_COMMIT();

    for (int c = 0; c < NC; c++) {
        int buf = c & 1;
        if (c + 1 < NC) {
            load_chunk(c + 1, buf ^ 1);
            CP_COMMIT();
            CP_WAIT(1);
        } else {
            CP_WAIT(0);
        }
        __syncthreads();

        const uint32_t* Ah = (const uint32_t*)(sm + buf * WBUFE);
        const uint32_t* Al = Ah + APL / 2;
        const uint32_t* Bh = Ah + APL;          // 2*APL elems = APL uint32
        const uint32_t* Bl = Bh + BPL / 2;
        #pragma unroll
        for (int ks = 0; ks < 4; ks++) {
            int kw = ks * 8;
            uint32_t ahi[4][4], alo[4][4], bhi[4][2], blo[4][2];
            #pragma unroll
            for (int mi = 0; mi < 4; mi++) {
                int r0 = (wm * 64 + mi * 16 + fr) * (PITCH/2) + kw + fc;
                int r1 = r0 + 8 * (PITCH/2);
                ahi[mi][0] = Ah[r0];     ahi[mi][1] = Ah[r1];
                ahi[mi][2] = Ah[r0 + 4]; ahi[mi][3] = Ah[r1 + 4];
                alo[mi][0] = Al[r0];     alo[mi][1] = Al[r1];
                alo[mi][2] = Al[r0 + 4]; alo[mi][3] = Al[r1 + 4];
            }
            #pragma unroll
            for (int ni = 0; ni < 4; ni++) {
                int n0 = (wn * 32 + ni * 8 + fr) * (PITCH/2) + kw + fc;
                bhi[ni][0] = Bh[n0]; bhi[ni][1] = Bh[n0 + 4];
                blo[ni][0] = Bl[n0]; blo[ni][1] = Bl[n0 + 4];
            }
            #pragma unroll
            for (int mi = 0; mi < 4; mi++)
                #pragma unroll
                for (int ni = 0; ni < 4; ni++) {
                    mma_bf16(acc[mi][ni], ahi[mi], bhi[ni]);
                    mma_bf16(acc[mi][ni], alo[mi], bhi[ni]);
                    mma_bf16(acc[mi][ni], ahi[mi], blo[ni]);
                }
        }
        __syncthreads();
    }

    // ---- fused epilogue: bias + leaky -> smem tile -> row LN -> output ----
    float* tile = (float*)sm;
    const int TP = 264;
    #pragma unroll
    for (int mi = 0; mi < 4; mi++) {
        int r0 = wm * 64 + mi * 16 + fr;
        #pragma unroll
        for (int ni = 0; ni < 4; ni++) {
            int col = wn * 32 + ni * 8 + fc * 2;
            float2 bb = *(const float2*)(bias + col);
            float2 u0, u1;
            u0.x = leaky(acc[mi][ni][0] + bb.x);
            u0.y = leaky(acc[mi][ni][1] + bb.y);
            u1.x = leaky(acc[mi][ni][2] + bb.x);
            u1.y = leaky(acc[mi][ni][3] + bb.y);
            *(float2*)&tile[r0 * TP + col]       = u0;
            *(float2*)&tile[(r0 + 8) * TP + col] = u1;
        }
    }
    __syncthreads();

    #pragma unroll
    for (int rr = 0; rr < 8; rr++) {
        int r = wid * 8 + rr;
        int c0 = lane * 8;
        float4 u0 = *(const float4*)&tile[r * TP + c0];
        float4 u1 = *(const float4*)&tile[r * TP + c0 + 4];
        float sum = u0.x+u0.y+u0.z+u0.w + u1.x+u1.y+u1.z+u1.w;
        float sq  = u0.x*u0.x+u0.y*u0.y+u0.z*u0.z+u0.w*u0.w
                  + u1.x*u1.x+u1.y*u1.y+u1.z*u1.z+u1.w*u1.w;
        #pragma unroll
        for (int o = 16; o > 0; o >>= 1) {
            sum += __shfl_xor_sync(0xffffffffu, sum, o);
            sq  += __shfl_xor_sync(0xffffffffu, sq,  o);
        }
        float m   = sum * (1.f/256.f);
        float inv = rsqrtf(sq * (1.f/256.f) - m * m + 1e-6f);
        float4 g0 = *(const float4*)(lg + c0), g1 = *(const float4*)(lg + c0 + 4);
        float4 b0 = *(const float4*)(lb + c0), b1 = *(const float4*)(lb + c0 + 4);
        float v[8];
        v[0]=(u0.x-m)*inv*g0.x+b0.x; v[1]=(u0.y-m)*inv*g0.y+b0.y;
        v[2]=(u0.z-m)*inv*g0.z+b0.z; v[3]=(u0.w-m)*inv*g0.w+b0.w;
        v[4]=(u1.x-m)*inv*g1.x+b1.x; v[5]=(u1.y-m)*inv*g1.y+b1.y;
        v[6]=(u1.z-m)*inv*g1.z+b1.z; v[7]=(u1.w-m)*inv*g1.w+b1.w;
        size_t grow = (size_t)(bm + r);
        if (EPI == 0) {
            uint4 ph, pl;
            pack8(v, ph, pl);
            ((uint4*)(Ohi + grow * 256))[lane] = ph;
            ((uint4*)(Olo + grow * 256))[lane] = pl;
        } else {
            float4 o0 = {v[0], v[1], v[2], v[3]};
            float4 o1 = {v[4], v[5], v[6], v[7]};
            *(float4*)(xout + grow * 256 + c0)     = o0;
            *(float4*)(xout + grow * 256 + c0 + 4) = o1;
        }
    }
}

// ---------------- attention scorer (x already LN2-normalized) -----------------
__global__ __launch_bounds__(256) void attn_kernel(const float* __restrict__ x,
                                                   const float* __restrict__ w1,
                                                   const float* __restrict__ b1,
                                                   const float* __restrict__ lng,
                                                   const float* __restrict__ lnb,
                                                   const float* __restrict__ w2,
                                                   const float* __restrict__ b2,
                                                   const int*  __restrict__ mask,
                                                   float* __restrict__ att) {
    __shared__ float xs[32][256];
    __shared__ float t1[32][65];
    __shared__ float mrow[32], irow[32];
    int t  = threadIdx.x;
    int r0 = blockIdx.x * 32;

    const float4* xsrc = (const float4*)(x + (size_t)r0 * 256);
    float4* xdst = (float4*)&xs[0][0];
    #pragma unroll
    for (int i = 0; i < 8; i++) xdst[t + i * 256] = xsrc[t + i * 256];
    __syncthreads();

    #pragma unroll
    for (int o = 0; o < 8; o++) {
        int idx = o * 256 + t;
        int r = idx >> 6, c = idx & 63;
        float acc = b1[c];
        #pragma unroll 4
        for (int k = 0; k < 256; k++) acc += xs[r][k] * w1[k * 64 + c];
        t1[r][c] = leaky(acc);
    }
    __syncthreads();

    if (t < 32) {
        float s = 0.f, q = 0.f;
        #pragma unroll
        for (int k = 0; k < 64; k++) { float v = t1[t][k]; s += v; q += v * v; }
        float m = s * (1.f / 64.f), var = q * (1.f / 64.f) - m * m;
        mrow[t] = m; irow[t] = rsqrtf(var + 1e-6f);
    }
    __syncthreads();
    #pragma unroll
    for (int o = 0; o < 8; o++) {
        int idx = o * 256 + t;
        int r = idx >> 6, c = idx & 63;
        t1[r][c] = (t1[r][c] - mrow[r]) * irow[r] * lng[c] + lnb[c];
    }
    __syncthreads();

    int r = t >> 3, hd = t & 7;
    float acc = b2[hd];
    #pragma unroll
    for (int k = 0; k < 64; k++) acc += t1[r][k] * w2[k * 8 + hd];
    int gr = r0 + r;
    int b = gr >> 10, l = gr & 1023;
    if (mask[b * 1024 + l] == 0) acc = -1e9f;
    att[((size_t)b * NH_ + hd) * L_ + l] = acc;
}

// ---------------- softmax ----------------
__global__ __launch_bounds__(256) void softmax_kernel(float* __restrict__ att) {
    __shared__ float s[256];
    float* row = att + (size_t)blockIdx.x * L_;
    int t = threadIdx.x;
    float v[4]; float mx = -1e30f;
    #pragma unroll
    for (int i = 0; i < 4; i++) { v[i] = row[t + i * 256]; mx = fmaxf(mx, v[i]); }
    s[t] = mx; __syncthreads();
    for (int st = 128; st > 0; st >>= 1) { if (t < st) s[t] = fmaxf(s[t], s[t + st]); __syncthreads(); }
    mx = s[0]; __syncthreads();
    float sum = 0.f;
    #pragma unroll
    for (int i = 0; i < 4; i++) { v[i] = expf(v[i] - mx); sum += v[i]; }
    s[t] = sum; __syncthreads();
    for (int st = 128; st > 0; st >>= 1) { if (t < st) s[t] += s[t + st]; __syncthreads(); }
    float inv = 1.f / s[0];
    #pragma unroll
    for (int i = 0; i < 4; i++) row[t + i * 256] = v[i] * inv;
}

// ---------------- pooling ----------------
__global__ __launch_bounds__(256) void pool_partial(const float* __restrict__ x,
                                                    const float* __restrict__ att,
                                                    float* __restrict__ part) {
    int chunk = blockIdx.x, b = blockIdx.y;
    int t = threadIdx.x;
    __shared__ float as[8][64];
    int l0 = chunk * 64;
    for (int i = t; i < 512; i += 256) {
        int hd = i >> 6, l = i & 63;
        as[hd][l] = att[((size_t)b * NH_ + hd) * L_ + l0 + l];
    }
    __syncthreads();
    float acc[8] = {};
    for (int l = 0; l < 64; l++) {
        float xv = x[((size_t)b * L_ + l0 + l) * H_ + t];
        #pragma unroll
        for (int hd = 0; hd < 8; hd++) acc[hd] += as[hd][l] * xv;
    }
    #pragma unroll
    for (int hd = 0; hd < 8; hd++)
        part[(((size_t)b * 16 + chunk) * NH_ + hd) * H_ + t] = acc[hd];
}

__global__ __launch_bounds__(256) void pool_reduce(const float* __restrict__ part,
                                                   float* __restrict__ h) {
    int hd = blockIdx.x, b = blockIdx.y, t = threadIdx.x;
    float s = 0.f;
    #pragma unroll
    for (int c = 0; c < 16; c++)
        s += part[(((size_t)b * 16 + c) * NH_ + hd) * H_ + t];
    h[(size_t)b * OH_ + hd * H_ + t] = s;
}

// ---------------- M=8 output GEMM: split-K partials ----------------
__global__ __launch_bounds__(256) void out_partial(const float* __restrict__ h,
                                                   const float* __restrict__ w,
                                                   float* __restrict__ part, int N) {
    __shared__ float hs[8][128];
    int t = threadIdx.x;
    int j = blockIdx.x * 256 + t;
    int k0 = blockIdx.y * 128;
    for (int i = t; i < 1024; i += 256)
        hs[i >> 7][i & 127] = h[(size_t)(i >> 7) * OH_ + k0 + (i & 127)];
    __syncthreads();
    if (j >= N) return;
    float acc[8] = {};
    const float* wp = w + (size_t)k0 * N + j;
    #pragma unroll 8
    for (int kk = 0; kk < 128; kk++) {
        float wv = wp[(size_t)kk * N];
        #pragma unroll
        for (int b = 0; b < 8; b++) acc[b] += hs[b][kk] * wv;
    }
    float* pp = part + (size_t)(blockIdx.y * 8) * N + j;
    #pragma unroll
    for (int b = 0; b < 8; b++) pp[(size_t)b * N] = acc[b];
}

// ---------------- fused reduce + leaky + LN2048 (output block 1) --------------
__global__ __launch_bounds__(256) void out1_finish(const float* __restrict__ part,
                                                   const float* __restrict__ bias,
                                                   const float* __restrict__ g,
                                                   const float* __restrict__ bb,
                                                   float* __restrict__ h1) {
    __shared__ float ws[16];
    int b = blockIdx.x, t = threadIdx.x;
    int wid = t >> 5, lane = t & 31;
    float v[8];
    float sum = 0.f, sq = 0.f;
    #pragma unroll
    for (int i = 0; i < 8; i++) {
        int j = t + i * 256;
        float s = 0.f;
        #pragma unroll
        for (int ks = 0; ks < 16; ks++)
            s += part[(size_t)(ks * 8 + b) * OH_ + j];
        float val = leaky(s + bias[j]);
        v[i] = val; sum += val; sq += val * val;
    }
    #pragma unroll
    for (int o = 16; o > 0; o >>= 1) {
        sum += __shfl_xor_sync(0xffffffffu, sum, o);
        sq  += __shfl_xor_sync(0xffffffffu, sq,  o);
    }
    if (lane == 0) { ws[wid] = sum; ws[8 + wid] = sq; }
    __syncthreads();
    float s8 = ws[lane & 7], q8 = ws[8 + (lane & 7)];
    #pragma unroll
    for (int o = 4; o > 0; o >>= 1) {
        s8 += __shfl_xor_sync(0xffffffffu, s8, o);
        q8 += __shfl_xor_sync(0xffffffffu, q8, o);
    }
    float m   = s8 * (1.f / OH_);
    float inv = rsqrtf(q8 * (1.f / OH_) - m * m + 1e-6f);
    #pragma unroll
    for (int i = 0; i < 8; i++) {
        int j = t + i * 256;
        h1[(size_t)b * OH_ + j] = (v[i] - m) * inv * g[j] + bb[j];
    }
}

// ---------------- output block 2 reduce: sigmoid, write pT[j][8] --------------
__global__ __launch_bounds__(256) void out2_reduce(const float* __restrict__ part,
                                                   const float* __restrict__ bias,
                                                   float* __restrict__ pT) {
    int j = blockIdx.x * 256 + threadIdx.x;
    if (j >= LBL_) return;
    float s[8] = {};
    #pragma unroll
    for (int ks = 0; ks < 16; ks++)
        #pragma unroll
        for (int b = 0; b < 8; b++)
            s[b] += part[(size_t)(ks * 8 + b) * LBL_ + j];
    float bb = bias[j];
    #pragma unroll
    for (int b = 0; b < 8; b++)
        s[b] = 1.f / (1.f + expf(-(s[b] + bb)));
    float4 q0 = {s[0], s[1], s[2], s[3]};
    float4 q1 = {s[4], s[5], s[6], s[7]};
    float4* pp = (float4*)(pT + (size_t)j * 8);
    pp[0] = q0; pp[1] = q1;
}

// ---------------- GO max-propagation (pT layout, float2 CM scan) --------------
__global__ __launch_bounds__(256) void maxprop_kernel(const float* __restrict__ pT,
                                                      const float* __restrict__ CM,
                                                      float* __restrict__ out) {
    int i = blockIdx.x, t = threadIdx.x;
    __shared__ float red[256][9];
    float acc[8] = {};
    const float2* row2 = (const float2*)(CM + (size_t)i * LBL_);
    const int NJ2 = LBL_ / 2;
    for (int j2 = t; j2 < NJ2; j2 += 256) {
        float2 c = row2[j2];
        if (c.x != 0.f) {
            const float4* pp = (const float4*)(pT + (size_t)(2 * j2) * 8);
            float4 a = pp[0], d = pp[1];
            acc[0]=fmaxf(acc[0],a.x*c.x); acc[1]=fmaxf(acc[1],a.y*c.x);
            acc[2]=fmaxf(acc[2],a.z*c.x); acc[3]=fmaxf(acc[3],a.w*c.x);
            acc[4]=fmaxf(acc[4],d.x*c.x); acc[5]=fmaxf(acc[5],d.y*c.x);
            acc[6]=fmaxf(acc[6],d.z*c.x); acc[7]=fmaxf(acc[7],d.w*c.x);
        }
        if (c.y != 0.f) {
            const float4* pp = (const float4*)(pT + (size_t)(2 * j2 + 1) * 8);
            float4 a = pp[0], d = pp[1];
            acc[0]=fmaxf(acc[0],a.x*c.y); acc[1]=fmaxf(acc[1],a.y*c.y);
            acc[2]=fmaxf(acc[2],a.z*c.y); acc[3]=fmaxf(acc[3],a.w*c.y);
            acc[4]=fmaxf(acc[4],d.x*c.y); acc[5]=fmaxf(acc[5],d.y*c.y);
            acc[6]=fmaxf(acc[6],d.z*c.y); acc[7]=fmaxf(acc[7],d.w*c.y);
        }
    }
    #pragma unroll
    for (int b = 0; b < 8; b++) red[t][b] = acc[b];
    __syncthreads();
    for (int s = 128; s > 0; s >>= 1) {
        if (t < s) {
            #pragma unroll
            for (int b = 0; b < 8; b++) red[t][b] = fmaxf(red[t][b], red[t + s][b]);
        }
        __syncthreads();
    }
    if (t < 8) out[(size_t)t * LBL_ + i] = red[0][t];
}

// ---------------- launch ----------------
extern "C" void kernel_launch(void* const* d_in, const int* in_sizes, int n_in,
                              void* d_out, int out_size) {
    const float* h_V   = (const float*)d_in[0];
    const int*   mask  = (const int*)  d_in[1];
    const float* ln0_g = (const float*)d_in[2];
    const float* ln0_b = (const float*)d_in[3];
    const float* w_in  = (const float*)d_in[4];
    const float* b_in  = (const float*)d_in[5];
    const float* ln1_g = (const float*)d_in[6];
    const float* ln1_b = (const float*)d_in[7];
    const float* w_h   = (const float*)d_in[8];
    const float* b_h   = (const float*)d_in[9];
    const float* ln2_g = (const float*)d_in[10];
    const float* ln2_b = (const float*)d_in[11];
    const float* a_w1  = (const float*)d_in[12];
    const float* a_b1  = (const float*)d_in[13];
    const float* a_lng = (const float*)d_in[14];
    const float* a_lnb = (const float*)d_in[15];
    const float* a_w2  = (const float*)d_in[16];
    const float* a_b2  = (const float*)d_in[17];
    const float* o_w1  = (const float*)d_in[18];
    const float* o_b1  = (const float*)d_in[19];
    const float* o_lng = (const float*)d_in[20];
    const float* o_lnb = (const float*)d_in[21];
    const float* o_w2  = (const float*)d_in[22];
    const float* o_b2  = (const float*)d_in[23];
    const float* CM    = (const float*)d_in[24];
    float* out = (float*)d_out;

    float *x2, *att, *part, *hb, *h1, *pT, *op1, *op2;
    unsigned short *Ahi, *Alo, *A2hi, *A2lo, *Whi, *Wlo, *W2hi, *W2lo;
    cudaGetSymbolAddress((void**)&x2,    g_x2);
    cudaGetSymbolAddress((void**)&att,   g_att);
    cudaGetSymbolAddress((void**)&part,  g_part);
    cudaGetSymbolAddress((void**)&hb,    g_h);
    cudaGetSymbolAddress((void**)&h1,    g_h1);
    cudaGetSymbolAddress((void**)&pT,    g_p);
    cudaGetSymbolAddress((void**)&op1,   g_op1);
    cudaGetSymbolAddress((void**)&op2,   g_op2);
    cudaGetSymbolAddress((void**)&Ahi,   g_Ahi);
    cudaGetSymbolAddress((void**)&Alo,   g_Alo);
    cudaGetSymbolAddress((void**)&A2hi,  g_A2hi);
    cudaGetSymbolAddress((void**)&A2lo,  g_A2lo);
    cudaGetSymbolAddress((void**)&Whi,   g_Whi);
    cudaGetSymbolAddress((void**)&Wlo,   g_Wlo);
    cudaGetSymbolAddress((void**)&W2hi,  g_W2hi);
    cudaGetSymbolAddress((void**)&W2lo,  g_W2lo);

    cudaFuncSetAttribute(gemm_wide<0>, cudaFuncAttributeMaxDynamicSharedMemorySize, WGS);
    cudaFuncSetAttribute(gemm_wide<1>, cudaFuncAttributeMaxDynamicSharedMemorySize, WGS);

    // input + hidden blocks (LN0 in convA1024; LN1/LN2 fused in GEMM epilogues)
    convA1024<<<ROWS_/2, 256>>>(h_V, Ahi, Alo, ln0_g, ln0_b);
    convWB<<<dim3(8, 32, 2), 256>>>(w_in, Whi, Wlo, w_h, W2hi, W2lo);
    gemm_wide<0><<<ROWS_/128, 512, WGS>>>(Ahi, Alo, Whi, Wlo, b_in,
                                          ln1_g, ln1_b, A2hi, A2lo, nullptr, F_);
    gemm_wide<1><<<ROWS_/128, 512, WGS>>>(A2hi, A2lo, W2hi, W2lo, b_h,
                                          ln2_g, ln2_b, nullptr, nullptr, x2, H_);

    // attention pooling (x2 already LN2-normalized)
    attn_kernel<<<ROWS_/32, 256>>>(x2, a_w1, a_b1, a_lng, a_lnb, a_w2, a_b2, mask, att);
    softmax_kernel<<<B_*NH_, 256>>>(att);
    pool_partial<<<dim3(16, B_), 256>>>(x2, att, part);
    pool_reduce<<<dim3(NH_, B_), 256>>>(part, hb);

    // output block (split-K; reduce fused with LN for block 1)
    out_partial<<<dim3(OH_/256, 16), 256>>>(hb, o_w1, op1, OH_);
    out1_finish<<<B_, 256>>>(op1, o_b1, o_lng, o_lnb, h1);
    out_partial<<<dim3((LBL_+255)/256, 16), 256>>>(h1, o_w2, op2, LBL_);
    out2_reduce<<<(LBL_+255)/256, 256>>>(op2, o_b2, pT);

    // GO hierarchy max-product
    maxprop_kernel<<<LBL_, 256>>>(pT, CM, out);
}